// round 1
// baseline (speedup 1.0000x reference)
#include <cuda_runtime.h>
#include <math.h>

#define NB 8
#define NL 48
#define NT 512
#define HD 128
#define NG 10
#define M_TOTAL (NB*NL*NT)          // 196608

#define OFF_PI  0
#define OFF_SIG (M_TOTAL*NG)        // 1966080
#define OFF_MU  (2*M_TOTAL*NG)      // 3932160
#define OFF_D   (3*M_TOTAL*NG)      // 5898240
#define OFF_CB  (3*M_TOTAL*NG + M_TOTAL) // 6094848

// scratch (device globals: no allocation)
__device__ float g_Al[NB*NL*HD];    // 384 x 128
__device__ float g_At[NB*NT*HD];    // 4096 x 128

__device__ __forceinline__ float elu1(float x) {
    return x > 0.0f ? x : (__expf(x) - 1.0f);
}

// ---------------------------------------------------------------------------
// Precompute: A_l = s*(lig_s@W1^T + b1 - mean) + beta ;  A_t = s*(pro_s@W1^T)
// with s = gamma * rsqrt(var + eps). Then z = A_l + A_t equals the BN output.
// ---------------------------------------------------------------------------
#define PRE_ROWS 32
#define PRE_THREADS 256
#define W1T_PITCH 132
#define PRE_SMEM ((PRE_ROWS*HD + HD*W1T_PITCH)*sizeof(float))

__global__ void __launch_bounds__(PRE_THREADS)
precompute_kernel(const float* __restrict__ lig_s, const float* __restrict__ pro_s,
                  const float* __restrict__ W1,    const float* __restrict__ b1,
                  const float* __restrict__ bn_g,  const float* __restrict__ bn_b,
                  const float* __restrict__ bn_m,  const float* __restrict__ bn_v)
{
    extern __shared__ float sm[];
    float* Xs  = sm;                      // [32][128]
    float* W1t = sm + PRE_ROWS*HD;        // [128][132]  (transposed, padded)

    const int tid  = threadIdx.x;
    const int row0 = blockIdx.x * PRE_ROWS;
    const bool is_lig = (row0 < NB*NL);   // blocks 0..11 are ligand rows

    // load 32 input rows (float4, coalesced)
    const float4* src = is_lig ? (const float4*)(lig_s + (size_t)row0*HD)
                               : (const float4*)(pro_s + (size_t)(row0 - NB*NL)*HD);
    float4* Xs4 = (float4*)Xs;
    #pragma unroll
    for (int i = 0; i < (PRE_ROWS*HD/4)/PRE_THREADS; i++)
        Xs4[tid + i*PRE_THREADS] = src[tid + i*PRE_THREADS];

    // load W1 transposed into smem (padded pitch avoids STS conflicts)
    for (int idx = tid; idx < HD*HD; idx += PRE_THREADS) {
        int h = idx >> 7, k = idx & (HD-1);
        W1t[k*W1T_PITCH + h] = W1[idx];
    }
    __syncthreads();

    const int r  = tid >> 3;          // 0..31 : row within tile
    const int h0 = (tid & 7) << 4;    // 0,16,...,112 : 16 output dims

    float acc[16];
    #pragma unroll
    for (int j = 0; j < 16; j++) acc[j] = 0.0f;

    #pragma unroll 4
    for (int k = 0; k < HD; k++) {
        float x = Xs[r*HD + k];
        const float4* w4 = (const float4*)(&W1t[k*W1T_PITCH + h0]);
        float w[16];
        #pragma unroll
        for (int q = 0; q < 4; q++) {
            float4 v = w4[q];
            w[4*q] = v.x; w[4*q+1] = v.y; w[4*q+2] = v.z; w[4*q+3] = v.w;
        }
        #pragma unroll
        for (int j = 0; j < 16; j++) acc[j] = fmaf(x, w[j], acc[j]);
    }

    const int row = row0 + r;
    if (is_lig) {
        #pragma unroll
        for (int j = 0; j < 16; j++) {
            int h = h0 + j;
            float s = bn_g[h] * rsqrtf(bn_v[h] + 1e-5f);
            g_Al[row*HD + h] = s * (acc[j] + b1[h] - bn_m[h]) + bn_b[h];
        }
    } else {
        const int prow = row - NB*NL;
        #pragma unroll
        for (int j = 0; j < 16; j++) {
            int h = h0 + j;
            float s = bn_g[h] * rsqrtf(bn_v[h] + 1e-5f);
            g_At[prow*HD + h] = s * acc[j];
        }
    }
}

// ---------------------------------------------------------------------------
// Main pair kernel: per (l,t): e = elu(A_l + A_t); 30 dots with W heads;
// softmax(pi), elu+1.1 (sigma), elu+1.0 (mu), dist, batch id.
// Tile: 8 ligands x 32 proteins per block, 128 threads, 2 pairs/thread.
// ---------------------------------------------------------------------------
#define L_TILE 8
#define T_TILE 32
#define AT_PITCH 132
#define SW_PITCH 36
#define MAIN_THREADS 128

__global__ void __launch_bounds__(MAIN_THREADS)
pair_kernel(const float* __restrict__ lig_pos, const float* __restrict__ pro_pos,
            const float* __restrict__ W_pi,  const float* __restrict__ b_pi,
            const float* __restrict__ W_sig, const float* __restrict__ b_sig,
            const float* __restrict__ W_mu,  const float* __restrict__ b_mu,
            float* __restrict__ out)
{
    __shared__ float sAl[L_TILE*HD];          // 1024 f
    __shared__ float sAt[T_TILE*AT_PITCH];    // 4224 f (padded)
    __shared__ float sW[HD*SW_PITCH];         // [h][g] g=0..9 pi,10..19 sig,20..29 mu
    __shared__ float sBias[32];
    __shared__ float sPl[L_TILE*4];
    __shared__ float sPt[T_TILE*4];

    const int tid = threadIdx.x;
    const int b  = blockIdx.z;
    const int l0 = blockIdx.y * L_TILE;
    const int t0 = blockIdx.x * T_TILE;

    {
        const float4* srl = (const float4*)(g_Al + (size_t)(b*NL + l0)*HD);
        float4* dl = (float4*)sAl;
        #pragma unroll
        for (int i = 0; i < (L_TILE*HD/4)/MAIN_THREADS; i++)
            dl[tid + i*MAIN_THREADS] = srl[tid + i*MAIN_THREADS];
    }
    {
        const float4* srt = (const float4*)(g_At + (size_t)(b*NT + t0)*HD);
        float4* dt = (float4*)sAt;   // pitch 33 float4
        #pragma unroll
        for (int i = 0; i < (T_TILE*HD/4)/MAIN_THREADS; i++) {
            int idx = tid + i*MAIN_THREADS;
            int t = idx >> 5, hq = idx & 31;
            dt[t*(AT_PITCH/4) + hq] = srt[idx];
        }
    }
    for (int idx = tid; idx < NG*HD; idx += MAIN_THREADS) {
        int g = idx >> 7, h = idx & (HD-1);
        sW[h*SW_PITCH + g]      = W_pi[idx];
        sW[h*SW_PITCH + 10 + g] = W_sig[idx];
        sW[h*SW_PITCH + 20 + g] = W_mu[idx];
    }
    for (int h = tid; h < HD; h += MAIN_THREADS) {
        sW[h*SW_PITCH + 30] = 0.0f;
        sW[h*SW_PITCH + 31] = 0.0f;
    }
    if (tid < NG) {
        sBias[tid]      = b_pi[tid];
        sBias[10 + tid] = b_sig[tid];
        sBias[20 + tid] = b_mu[tid];
    }
    if (tid < L_TILE*3) {
        int l = tid / 3, c = tid % 3;
        sPl[l*4 + c] = lig_pos[(size_t)(b*NL + l0 + l)*3 + c];
    }
    if (tid < T_TILE*3) {
        int t = tid / 3, c = tid % 3;
        sPt[t*4 + c] = pro_pos[(size_t)(b*NT + t0 + t)*3 + c];
    }
    __syncthreads();

    const int lt = tid >> 4;    // 0..7
    const int tt = tid & 15;    // 0..15 ; pairs (lt,tt) and (lt,tt+16)

    float acc0[30], acc1[30];
    #pragma unroll
    for (int g = 0; g < 30; g++) { acc0[g] = 0.0f; acc1[g] = 0.0f; }

    const float4* al4 = (const float4*)(sAl + lt*HD);
    const float4* a04 = (const float4*)(sAt + tt*AT_PITCH);
    const float4* a14 = (const float4*)(sAt + (tt+16)*AT_PITCH);

    #pragma unroll 2
    for (int hq = 0; hq < HD/4; hq++) {
        float4 al = al4[hq];
        float4 v0 = a04[hq];
        float4 v1 = a14[hq];
        float e0[4], e1[4];
        e0[0] = elu1(al.x + v0.x); e0[1] = elu1(al.y + v0.y);
        e0[2] = elu1(al.z + v0.z); e0[3] = elu1(al.w + v0.w);
        e1[0] = elu1(al.x + v1.x); e1[1] = elu1(al.y + v1.y);
        e1[2] = elu1(al.z + v1.z); e1[3] = elu1(al.w + v1.w);
        #pragma unroll
        for (int j = 0; j < 4; j++) {
            const float4* wr = (const float4*)(sW + (hq*4 + j)*SW_PITCH);
            float w[32];
            #pragma unroll
            for (int q = 0; q < 8; q++) {
                float4 v = wr[q];
                w[4*q] = v.x; w[4*q+1] = v.y; w[4*q+2] = v.z; w[4*q+3] = v.w;
            }
            float ea = e0[j], eb = e1[j];
            #pragma unroll
            for (int g = 0; g < 30; g++) {
                acc0[g] = fmaf(ea, w[g], acc0[g]);
                acc1[g] = fmaf(eb, w[g], acc1[g]);
            }
        }
    }

    const int l = l0 + lt;
    const float plx = sPl[lt*4], ply = sPl[lt*4+1], plz = sPl[lt*4+2];

#define DO_PAIR(ACC, TLOC) do {                                               \
    const int tl = (TLOC);                                                    \
    const int t  = t0 + tl;                                                   \
    const size_t p = (size_t)((b*NL + l)*NT) + t;                             \
    float y[10]; float mx = -1e30f;                                           \
    _Pragma("unroll")                                                         \
    for (int g = 0; g < NG; g++) { y[g] = ACC[g] + sBias[g]; mx = fmaxf(mx, y[g]); } \
    float ssum = 0.0f;                                                        \
    _Pragma("unroll")                                                         \
    for (int g = 0; g < NG; g++) { y[g] = __expf(y[g] - mx); ssum += y[g]; }  \
    float inv = 1.0f / ssum;                                                  \
    float2* po = (float2*)(out + OFF_PI + p*NG);                              \
    _Pragma("unroll")                                                         \
    for (int g = 0; g < 5; g++) po[g] = make_float2(y[2*g]*inv, y[2*g+1]*inv);\
    float2* so = (float2*)(out + OFF_SIG + p*NG);                             \
    _Pragma("unroll")                                                         \
    for (int g = 0; g < 5; g++) {                                             \
        float s0 = elu1(ACC[10+2*g]   + sBias[10+2*g])   + 1.1f;              \
        float s1 = elu1(ACC[10+2*g+1] + sBias[10+2*g+1]) + 1.1f;              \
        so[g] = make_float2(s0, s1);                                          \
    }                                                                         \
    float2* mo = (float2*)(out + OFF_MU + p*NG);                              \
    _Pragma("unroll")                                                         \
    for (int g = 0; g < 5; g++) {                                             \
        float m0 = elu1(ACC[20+2*g]   + sBias[20+2*g])   + 1.0f;              \
        float m1 = elu1(ACC[20+2*g+1] + sBias[20+2*g+1]) + 1.0f;              \
        mo[g] = make_float2(m0, m1);                                          \
    }                                                                         \
    float dx = plx - sPt[tl*4];                                               \
    float dy = ply - sPt[tl*4+1];                                             \
    float dz = plz - sPt[tl*4+2];                                             \
    out[OFF_D  + p] = sqrtf(dx*dx + dy*dy + dz*dz);                           \
    out[OFF_CB + p] = (float)b;                                               \
} while (0)

    DO_PAIR(acc0, tt);
    DO_PAIR(acc1, tt + 16);
#undef DO_PAIR
}

// ---------------------------------------------------------------------------
extern "C" void kernel_launch(void* const* d_in, const int* in_sizes, int n_in,
                              void* d_out, int out_size)
{
    (void)in_sizes; (void)n_in; (void)out_size;
    const float* lig_s   = (const float*)d_in[0];
    const float* lig_pos = (const float*)d_in[1];
    // d_in[2] lig_batch (int64) unused — uniform segments
    const float* pro_s   = (const float*)d_in[3];
    const float* pro_pos = (const float*)d_in[4];
    // d_in[5] pro_batch (int64) unused
    const float* W1      = (const float*)d_in[6];
    const float* b1      = (const float*)d_in[7];
    const float* bn_g    = (const float*)d_in[8];
    const float* bn_b    = (const float*)d_in[9];
    const float* bn_m    = (const float*)d_in[10];
    const float* bn_v    = (const float*)d_in[11];
    const float* W_pi    = (const float*)d_in[12];
    const float* b_pi    = (const float*)d_in[13];
    const float* W_sig   = (const float*)d_in[14];
    const float* b_sig   = (const float*)d_in[15];
    const float* W_mu    = (const float*)d_in[16];
    const float* b_mu    = (const float*)d_in[17];
    float* out = (float*)d_out;

    cudaFuncSetAttribute(precompute_kernel,
                         cudaFuncAttributeMaxDynamicSharedMemorySize, (int)PRE_SMEM);
    precompute_kernel<<<(NB*NL + NB*NT)/PRE_ROWS, PRE_THREADS, PRE_SMEM>>>(
        lig_s, pro_s, W1, b1, bn_g, bn_b, bn_m, bn_v);

    pair_kernel<<<dim3(NT/T_TILE, NL/L_TILE, NB), MAIN_THREADS>>>(
        lig_pos, pro_pos, W_pi, b_pi, W_sig, b_sig, W_mu, b_mu, out);
}